// round 1
// baseline (speedup 1.0000x reference)
#include <cuda_runtime.h>

#define Bc 8
#define Cc 96
#define Hc 256
#define Wc 256
#define TH 8                    // output rows per block
#define HALO 4                  // max halo (mf: conv1 + avg7 radius 3)
#define RROWS (TH + 2*HALO)     // 16 raw rows
#define RW (Wc + 2*HALO)        // 264 row width (cols -4..259)
#define VROWS (TH + 2)          // 10 rows of vertical sums / bp / hp

// valid-count for avgpool (count_include_pad=False), H==W==256
__device__ __forceinline__ float cntf(int i, int p) {
    int lo = i - p; if (lo < 0) lo = 0;
    int hi = i + p; if (hi > Hc - 1) hi = Hc - 1;
    return (float)(hi - lo + 1);
}

__device__ __forceinline__ float bn_silu(float acc, float scal, float shft) {
    float v = fmaf(acc, scal, shft);
    return v * __fdividef(1.f, 1.f + __expf(-v));
}

// 3x3 conv over a VROWS x (W+2) buffer (stride RW), rolling register window.
__device__ __forceinline__ void conv3_emit(const float* __restrict__ bp,
                                           const float* __restrict__ sw,
                                           float scal, float shft,
                                           float* __restrict__ op, int t) {
    float w0 = sw[0], w1 = sw[1], w2 = sw[2];
    float w3 = sw[3], w4 = sw[4], w5 = sw[5];
    float w6 = sw[6], w7 = sw[7], w8 = sw[8];
    float a0 = bp[t],      a1 = bp[t + 1],      a2 = bp[t + 2];
    float b0 = bp[RW + t], b1 = bp[RW + t + 1], b2 = bp[RW + t + 2];
#pragma unroll
    for (int orow = 0; orow < TH; orow++) {
        const float* r = bp + (orow + 2) * RW + t;
        float c0 = r[0], c1 = r[1], c2 = r[2];
        float acc = w0 * a0;
        acc = fmaf(w1, a1, acc); acc = fmaf(w2, a2, acc);
        acc = fmaf(w3, b0, acc); acc = fmaf(w4, b1, acc); acc = fmaf(w5, b2, acc);
        acc = fmaf(w6, c0, acc); acc = fmaf(w7, c1, acc); acc = fmaf(w8, c2, acc);
        op[orow * Wc] = bn_silu(acc, scal, shft);
        a0 = b0; a1 = b1; a2 = b2;
        b0 = c0; b1 = c1; b2 = c2;
    }
}

__global__ __launch_bounds__(256) void trifreq_kernel(
    const float* __restrict__ x,
    const float* __restrict__ w_lo,
    const float* __restrict__ w_mf,
    const float* __restrict__ w_hf,
    const float* __restrict__ bn_gamma,
    const float* __restrict__ bn_beta,
    const float* __restrict__ bn_mean,
    const float* __restrict__ bn_var,
    float* __restrict__ out)
{
    __shared__ float s_raw[RROWS * RW];   // 16*264 raw tile (reused as bp for mf)
    __shared__ float s_v3[VROWS * RW];    // vertical 3-sums
    __shared__ float s_v7[VROWS * RW];    // vertical 7-sums (reused as hp for hf)
    __shared__ float s_w[25];

    const int t = threadIdx.x;
    const int tileY = blockIdx.x;
    const int ch = blockIdx.y;
    const int b = blockIdx.z;
    const int group = ch >> 5;   // 0=lo, 1=mf, 2=hf
    const int k = ch & 31;
    const int rowBase = tileY * TH;

    // weights for this channel
    if (group == 0)      { if (t < 25) s_w[t] = w_lo[k * 25 + t]; }
    else if (group == 1) { if (t < 9)  s_w[t] = w_mf[k * 9 + t]; }
    else                 { if (t < 9)  s_w[t] = w_hf[k * 9 + t]; }

    // load raw tile (zero-padded outside image)
    const float* xp = x + (size_t)(b * Cc + ch) * Hc * Wc;
    for (int idx = t; idx < RROWS * RW; idx += 256) {
        int rr = idx / RW;
        int cc = idx - rr * RW;
        int gr = rowBase + rr - HALO;
        int gc = cc - HALO;
        float v = 0.f;
        if ((unsigned)gr < (unsigned)Hc && (unsigned)gc < (unsigned)Wc)
            v = xp[gr * Wc + gc];
        s_raw[idx] = v;
    }
    __syncthreads();

    // channel shuffle folded into output channel index
    const int oc = 3 * k + group;
    const float inv  = bn_gamma[oc] * rsqrtf(bn_var[oc] + 1e-5f);
    const float shft = bn_beta[oc] - bn_mean[oc] * inv;
    float* op = out + ((size_t)(b * Cc + oc) * Hc + rowBase) * Wc + t;

    if (group == 0) {
        // ---- lo: direct 5x5 dwconv, rolling 5x5 register window ----
        float wr[25];
#pragma unroll
        for (int i = 0; i < 25; i++) wr[i] = s_w[i];
        float win[5][5];
#pragma unroll
        for (int r = 0; r < 4; r++)
#pragma unroll
            for (int c = 0; c < 5; c++)
                win[r][c] = s_raw[(r + 2) * RW + t + 2 + c];
#pragma unroll
        for (int orow = 0; orow < TH; orow++) {
#pragma unroll
            for (int c = 0; c < 5; c++)
                win[4][c] = s_raw[(orow + 6) * RW + t + 2 + c];
            float acc = 0.f;
#pragma unroll
            for (int r = 0; r < 5; r++)
#pragma unroll
                for (int c = 0; c < 5; c++)
                    acc = fmaf(wr[r * 5 + c], win[r][c], acc);
            op[orow * Wc] = bn_silu(acc, inv, shft);
#pragma unroll
            for (int r = 0; r < 4; r++)
#pragma unroll
                for (int c = 0; c < 5; c++)
                    win[r][c] = win[r + 1][c];
        }
    } else if (group == 1) {
        // ---- mf: (avg3 - avg7) band-pass, then 3x3 dwconv ----
        // vertical running sums per column
        for (int cc = t; cc < RW; cc += 256) {
            float s7 = 0.f;
#pragma unroll
            for (int r = 0; r < 7; r++) s7 += s_raw[r * RW + cc];
            float s3 = s_raw[2 * RW + cc] + s_raw[3 * RW + cc] + s_raw[4 * RW + cc];
#pragma unroll
            for (int vr = 0; vr < VROWS; vr++) {
                s_v3[vr * RW + cc] = s3;
                s_v7[vr * RW + cc] = s7;
                if (vr < VROWS - 1) {
                    s3 += s_raw[(vr + 5) * RW + cc] - s_raw[(vr + 2) * RW + cc];
                    s7 += s_raw[(vr + 7) * RW + cc] - s_raw[vr * RW + cc];
                }
            }
        }
        __syncthreads();
        // band-pass into s_raw (raw no longer needed). bp col bc ~ img col bc-1.
        for (int bc = t; bc < Wc + 2; bc += 256) {
            int gx = bc - 1;
            float icx3 = __fdividef(1.f, cntf(gx, 1));
            float icx7 = __fdividef(1.f, cntf(gx, 3));
#pragma unroll
            for (int br = 0; br < VROWS; br++) {
                int gy = rowBase + br - 1;
                float bpv = 0.f;
                if ((unsigned)gy < (unsigned)Hc && (unsigned)gx < (unsigned)Wc) {
                    float h3 = s_v3[br * RW + bc + 2] + s_v3[br * RW + bc + 3]
                             + s_v3[br * RW + bc + 4];
                    float h7 = 0.f;
#pragma unroll
                    for (int d = 0; d < 7; d++) h7 += s_v7[br * RW + bc + d];
                    float iy3 = __fdividef(1.f, cntf(gy, 1));
                    float iy7 = __fdividef(1.f, cntf(gy, 3));
                    bpv = h3 * icx3 * iy3 - h7 * icx7 * iy7;
                }
                s_raw[br * RW + bc] = bpv;
            }
        }
        __syncthreads();
        conv3_emit(s_raw, s_w, inv, shft, op, t);
    } else {
        // ---- hf: x - avg3 high-pass, then 3x3 dwconv ----
        for (int cc = t; cc < RW; cc += 256) {
            float s3 = s_raw[2 * RW + cc] + s_raw[3 * RW + cc] + s_raw[4 * RW + cc];
#pragma unroll
            for (int vr = 0; vr < VROWS; vr++) {
                s_v3[vr * RW + cc] = s3;
                if (vr < VROWS - 1)
                    s3 += s_raw[(vr + 5) * RW + cc] - s_raw[(vr + 2) * RW + cc];
            }
        }
        __syncthreads();
        // high-pass into s_v7. hp col hc ~ img col hc-1, row hr ~ img row rowBase+hr-1.
        for (int hc = t; hc < Wc + 2; hc += 256) {
            int gx = hc - 1;
            float icx3 = __fdividef(1.f, cntf(gx, 1));
#pragma unroll
            for (int hr = 0; hr < VROWS; hr++) {
                int gy = rowBase + hr - 1;
                float v = 0.f;
                if ((unsigned)gy < (unsigned)Hc && (unsigned)gx < (unsigned)Wc) {
                    float h3 = s_v3[hr * RW + hc + 2] + s_v3[hr * RW + hc + 3]
                             + s_v3[hr * RW + hc + 4];
                    float iy3 = __fdividef(1.f, cntf(gy, 1));
                    v = s_raw[(hr + 3) * RW + hc + 3] - h3 * icx3 * iy3;
                }
                s_v7[hr * RW + hc] = v;
            }
        }
        __syncthreads();
        conv3_emit(s_v7, s_w, inv, shft, op, t);
    }
}

extern "C" void kernel_launch(void* const* d_in, const int* in_sizes, int n_in,
                              void* d_out, int out_size) {
    (void)in_sizes; (void)n_in; (void)out_size;
    dim3 grid(Hc / TH, Cc, Bc);
    dim3 block(256);
    trifreq_kernel<<<grid, block>>>(
        (const float*)d_in[0], (const float*)d_in[1], (const float*)d_in[2],
        (const float*)d_in[3], (const float*)d_in[4], (const float*)d_in[5],
        (const float*)d_in[6], (const float*)d_in[7], (float*)d_out);
}

// round 2
// speedup vs baseline: 1.8795x; 1.8795x over previous
#include <cuda_runtime.h>

#define Bc 8
#define Cc 96
#define Hc 256
#define Wc 256
#define TH 8                    // output rows per block
#define HALO 4
#define RROWS 16                // raw rows in smem (full halo case)
#define NQ 66                   // float4 quads per smem row (cols -4..259)
#define QS 67                   // quad row stride (padded, odd)
#define VR 10                   // bp/vsum rows (out rows -1..8)

__device__ __forceinline__ float4 f4add(float4 a, float4 b) {
    return make_float4(a.x+b.x, a.y+b.y, a.z+b.z, a.w+b.w);
}
__device__ __forceinline__ float4 f4sub(float4 a, float4 b) {
    return make_float4(a.x-b.x, a.y-b.y, a.z-b.z, a.w-b.w);
}

// valid-count reciprocal for avgpool (count_include_pad=False), dim size 256
__device__ __forceinline__ float rcnt(int i, int p) {
    int lo = i - p; if (lo < 0) lo = 0;
    int hi = i + p; if (hi > Hc - 1) hi = Hc - 1;
    return __fdividef(1.f, (float)(hi - lo + 1));
}

__device__ __forceinline__ float bn_silu(float acc, float scal, float shft) {
    float v = fmaf(acc, scal, shft);
    return v * __fdividef(1.f, 1.f + __expf(-v));
}

// 3x3 dwconv over VR x NQ float4 buffer; thread -> quad j, rows r0 & r0+4
__device__ __forceinline__ void conv3v(const float4* __restrict__ buf,
                                       const float* __restrict__ sw,
                                       float scal, float shft,
                                       float* __restrict__ outp, int j, int r0) {
    float w[9];
#pragma unroll
    for (int i = 0; i < 9; i++) w[i] = sw[i];
#pragma unroll
    for (int rep = 0; rep < 2; rep++) {
        int r = r0 + rep * 4;
        float acc0 = 0.f, acc1 = 0.f, acc2 = 0.f, acc3 = 0.f;
#pragma unroll
        for (int kr = 0; kr < 3; kr++) {
            const float4* rp = buf + (r + kr) * QS + j;
            float4 A = rp[0], B = rp[1], C = rp[2];
            float c[12];
            c[0]=A.x; c[1]=A.y; c[2]=A.z; c[3]=A.w;
            c[4]=B.x; c[5]=B.y; c[6]=B.z; c[7]=B.w;
            c[8]=C.x; c[9]=C.y; c[10]=C.z; c[11]=C.w;
#pragma unroll
            for (int kc = 0; kc < 3; kc++) {
                float wv = w[kr * 3 + kc];
                acc0 = fmaf(wv, c[3 + kc], acc0);
                acc1 = fmaf(wv, c[4 + kc], acc1);
                acc2 = fmaf(wv, c[5 + kc], acc2);
                acc3 = fmaf(wv, c[6 + kc], acc3);
            }
        }
        float4 o;
        o.x = bn_silu(acc0, scal, shft);
        o.y = bn_silu(acc1, scal, shft);
        o.z = bn_silu(acc2, scal, shft);
        o.w = bn_silu(acc3, scal, shft);
        *(float4*)(outp + r * Wc + j * 4) = o;
    }
}

__global__ __launch_bounds__(256) void trifreq_kernel(
    const float* __restrict__ x,
    const float* __restrict__ w_lo,
    const float* __restrict__ w_mf,
    const float* __restrict__ w_hf,
    const float* __restrict__ bn_gamma,
    const float* __restrict__ bn_beta,
    const float* __restrict__ bn_mean,
    const float* __restrict__ bn_var,
    float* __restrict__ out)
{
    __shared__ float4 s_raw[RROWS * QS];  // raw tile; mf reuses rows 0..9 for bp
    __shared__ float4 s_a[VR * QS];       // vertical 3-sums
    __shared__ float4 s_b[VR * QS];       // vertical 7-sums (hf: high-pass)
    __shared__ float s_w[25];

    const int t = threadIdx.x;
    const int tileY = blockIdx.x;
    const int ch = blockIdx.y;
    const int b = blockIdx.z;
    const int group = ch >> 5;   // 0=lo, 1=mf, 2=hf
    const int k = ch & 31;
    const int rowBase = tileY * TH;

    if (group == 0)      { if (t < 25) s_w[t] = w_lo[k * 25 + t]; }
    else if (group == 1) { if (t < 9)  s_w[t] = w_mf[k * 9 + t]; }
    else                 { if (t < 9)  s_w[t] = w_hf[k * 9 + t]; }

    // ---- load raw tile as float4 (zero outside image) ----
    const float* xp = x + (size_t)(b * Cc + ch) * Hc * Wc;
    const int rlo = (group == 0) ? 2 : 0;     // lo only needs halo 2
    const int rhi = (group == 0) ? 14 : 16;
    const int nload = (rhi - rlo) * NQ;
    for (int idx = t; idx < nload; idx += 256) {
        int rr = idx / NQ + rlo;
        int q = idx - (rr - rlo) * NQ;
        int gr = rowBase + rr - HALO;
        float4 v = make_float4(0.f, 0.f, 0.f, 0.f);
        if (q >= 1 && q <= 64 && (unsigned)gr < (unsigned)Hc)
            v = *(const float4*)(xp + gr * Wc + (q - 1) * 4);
        s_raw[rr * QS + q] = v;
    }
    __syncthreads();

    // channel shuffle folded into output channel index
    const int oc = 3 * k + group;
    const float inv  = bn_gamma[oc] * rsqrtf(bn_var[oc] + 1e-5f);
    const float shft = bn_beta[oc] - bn_mean[oc] * inv;
    float* outp = out + ((size_t)(b * Cc + oc) * Hc + rowBase) * Wc;

    const int j = t & 63;        // output quad (img cols 4j..4j+3)
    const int r0 = t >> 6;       // row slot (rows r0 and r0+4)

    if (group == 0) {
        // ---- lo: direct 5x5 dwconv ----
        float w[25];
#pragma unroll
        for (int i = 0; i < 25; i++) w[i] = s_w[i];
#pragma unroll
        for (int rep = 0; rep < 2; rep++) {
            int r = r0 + rep * 4;
            float acc0 = 0.f, acc1 = 0.f, acc2 = 0.f, acc3 = 0.f;
#pragma unroll
            for (int kr = 0; kr < 5; kr++) {
                const float4* rp = s_raw + (r + 2 + kr) * QS + j;
                float4 A = rp[0], B = rp[1], C = rp[2];
                float c[12];
                c[0]=A.x; c[1]=A.y; c[2]=A.z; c[3]=A.w;
                c[4]=B.x; c[5]=B.y; c[6]=B.z; c[7]=B.w;
                c[8]=C.x; c[9]=C.y; c[10]=C.z; c[11]=C.w;
#pragma unroll
                for (int kc = 0; kc < 5; kc++) {
                    float wv = w[kr * 5 + kc];
                    acc0 = fmaf(wv, c[2 + kc], acc0);
                    acc1 = fmaf(wv, c[3 + kc], acc1);
                    acc2 = fmaf(wv, c[4 + kc], acc2);
                    acc3 = fmaf(wv, c[5 + kc], acc3);
                }
            }
            float4 o;
            o.x = bn_silu(acc0, inv, shft);
            o.y = bn_silu(acc1, inv, shft);
            o.z = bn_silu(acc2, inv, shft);
            o.w = bn_silu(acc3, inv, shft);
            *(float4*)(outp + r * Wc + j * 4) = o;
        }
        return;
    }

    if (group == 1) {
        // ---- mf: vertical 3- and 7-sums ----
        for (int idx = t; idx < 4 * NQ; idx += 256) {
            int chunk = idx / NQ;
            int q = idx - chunk * NQ;
            int vr0 = chunk * 3;                  // 0,3,6,9
            int nr = (chunk == 3) ? 1 : 3;
            const float4* col = s_raw + q;
            float4 s3 = f4add(f4add(col[(vr0+2)*QS], col[(vr0+3)*QS]), col[(vr0+4)*QS]);
            float4 s7 = s3;
            s7 = f4add(s7, col[(vr0+0)*QS]); s7 = f4add(s7, col[(vr0+1)*QS]);
            s7 = f4add(s7, col[(vr0+5)*QS]); s7 = f4add(s7, col[(vr0+6)*QS]);
            for (int i = 0; i < nr; i++) {
                int vr = vr0 + i;
                s_a[vr * QS + q] = s3;
                s_b[vr * QS + q] = s7;
                if (i + 1 < nr) {
                    s3 = f4add(s3, f4sub(col[(vr+5)*QS], col[(vr+2)*QS]));
                    s7 = f4add(s7, f4sub(col[(vr+7)*QS], col[(vr+0)*QS]));
                }
            }
        }
        __syncthreads();

        // ---- band-pass into s_raw rows 0..9 ----
        if (t < 2 * VR) {   // zero edge quads 0 and 65
            int q = (t < VR) ? 0 : 65;
            s_raw[(t % VR) * QS + q] = make_float4(0.f, 0.f, 0.f, 0.f);
        }
        {
            int q = j + 1;            // quads 1..64, img col base:
            int cb = j * 4;
            bool interior = (cb >= 3) && (cb <= 249);
            float icx3_0, icx3_1, icx3_2, icx3_3, icx7_0, icx7_1, icx7_2, icx7_3;
            if (interior) {
                icx3_0 = icx3_1 = icx3_2 = icx3_3 = (1.f / 3.f);
                icx7_0 = icx7_1 = icx7_2 = icx7_3 = (1.f / 7.f);
            } else {
                icx3_0 = rcnt(cb + 0, 1); icx3_1 = rcnt(cb + 1, 1);
                icx3_2 = rcnt(cb + 2, 1); icx3_3 = rcnt(cb + 3, 1);
                icx7_0 = rcnt(cb + 0, 3); icx7_1 = rcnt(cb + 1, 3);
                icx7_2 = rcnt(cb + 2, 3); icx7_3 = rcnt(cb + 3, 3);
            }
            for (int vr = r0; vr < VR; vr += 4) {
                int gy = rowBase + vr - 1;
                float4 o = make_float4(0.f, 0.f, 0.f, 0.f);
                if ((unsigned)gy < (unsigned)Hc) {
                    float iy3 = rcnt(gy, 1), iy7 = rcnt(gy, 3);
                    const float4* a = s_a + vr * QS + (q - 1);
                    const float4* bb = s_b + vr * QS + (q - 1);
                    float4 A = a[0], B = a[1], C = a[2];
                    float u3[12];
                    u3[0]=A.x; u3[1]=A.y; u3[2]=A.z; u3[3]=A.w;
                    u3[4]=B.x; u3[5]=B.y; u3[6]=B.z; u3[7]=B.w;
                    u3[8]=C.x; u3[9]=C.y; u3[10]=C.z; u3[11]=C.w;
                    float4 D = bb[0], E = bb[1], F = bb[2];
                    float u7[12];
                    u7[0]=D.x; u7[1]=D.y; u7[2]=D.z; u7[3]=D.w;
                    u7[4]=E.x; u7[5]=E.y; u7[6]=E.z; u7[7]=E.w;
                    u7[8]=F.x; u7[9]=F.y; u7[10]=F.z; u7[11]=F.w;
                    float h3_0 = u3[3] + u3[4] + u3[5];
                    float h3_1 = h3_0 + u3[6] - u3[3];
                    float h3_2 = h3_1 + u3[7] - u3[4];
                    float h3_3 = h3_2 + u3[8] - u3[5];
                    float h7_0 = u7[1]+u7[2]+u7[3]+u7[4]+u7[5]+u7[6]+u7[7];
                    float h7_1 = h7_0 + u7[8]  - u7[1];
                    float h7_2 = h7_1 + u7[9]  - u7[2];
                    float h7_3 = h7_2 + u7[10] - u7[3];
                    o.x = h3_0 * (icx3_0 * iy3) - h7_0 * (icx7_0 * iy7);
                    o.y = h3_1 * (icx3_1 * iy3) - h7_1 * (icx7_1 * iy7);
                    o.z = h3_2 * (icx3_2 * iy3) - h7_2 * (icx7_2 * iy7);
                    o.w = h3_3 * (icx3_3 * iy3) - h7_3 * (icx7_3 * iy7);
                }
                s_raw[vr * QS + q] = o;
            }
        }
        __syncthreads();
        conv3v(s_raw, s_w, inv, shft, outp, j, r0);
        return;
    }

    // ---- hf: vertical 3-sums ----
    for (int idx = t; idx < 4 * NQ; idx += 256) {
        int chunk = idx / NQ;
        int q = idx - chunk * NQ;
        int vr0 = chunk * 3;
        int nr = (chunk == 3) ? 1 : 3;
        const float4* col = s_raw + q;
        float4 s3 = f4add(f4add(col[(vr0+2)*QS], col[(vr0+3)*QS]), col[(vr0+4)*QS]);
        for (int i = 0; i < nr; i++) {
            int vr = vr0 + i;
            s_a[vr * QS + q] = s3;
            if (i + 1 < nr)
                s3 = f4add(s3, f4sub(col[(vr+5)*QS], col[(vr+2)*QS]));
        }
    }
    __syncthreads();

    // ---- high-pass into s_b ----
    if (t < 2 * VR) {
        int q = (t < VR) ? 0 : 65;
        s_b[(t % VR) * QS + q] = make_float4(0.f, 0.f, 0.f, 0.f);
    }
    {
        int q = j + 1;
        int cb = j * 4;
        bool interior = (cb >= 1) && (cb <= 251);
        float icx3_0, icx3_1, icx3_2, icx3_3;
        if (interior) {
            icx3_0 = icx3_1 = icx3_2 = icx3_3 = (1.f / 3.f);
        } else {
            icx3_0 = rcnt(cb + 0, 1); icx3_1 = rcnt(cb + 1, 1);
            icx3_2 = rcnt(cb + 2, 1); icx3_3 = rcnt(cb + 3, 1);
        }
        for (int vr = r0; vr < VR; vr += 4) {
            int gy = rowBase + vr - 1;
            float4 o = make_float4(0.f, 0.f, 0.f, 0.f);
            if ((unsigned)gy < (unsigned)Hc) {
                float iy3 = rcnt(gy, 1);
                const float4* a = s_a + vr * QS + (q - 1);
                float4 A = a[0], B = a[1], C = a[2];
                float u3[12];
                u3[0]=A.x; u3[1]=A.y; u3[2]=A.z; u3[3]=A.w;
                u3[4]=B.x; u3[5]=B.y; u3[6]=B.z; u3[7]=B.w;
                u3[8]=C.x; u3[9]=C.y; u3[10]=C.z; u3[11]=C.w;
                float h3_0 = u3[3] + u3[4] + u3[5];
                float h3_1 = h3_0 + u3[6] - u3[3];
                float h3_2 = h3_1 + u3[7] - u3[4];
                float h3_3 = h3_2 + u3[8] - u3[5];
                float4 rawv = s_raw[(vr + 3) * QS + q];
                o.x = rawv.x - h3_0 * (icx3_0 * iy3);
                o.y = rawv.y - h3_1 * (icx3_1 * iy3);
                o.z = rawv.z - h3_2 * (icx3_2 * iy3);
                o.w = rawv.w - h3_3 * (icx3_3 * iy3);
            }
            s_b[vr * QS + q] = o;
        }
    }
    __syncthreads();
    conv3v(s_b, s_w, inv, shft, outp, j, r0);
}

extern "C" void kernel_launch(void* const* d_in, const int* in_sizes, int n_in,
                              void* d_out, int out_size) {
    (void)in_sizes; (void)n_in; (void)out_size;
    dim3 grid(Hc / TH, Cc, Bc);
    dim3 block(256);
    trifreq_kernel<<<grid, block>>>(
        (const float*)d_in[0], (const float*)d_in[1], (const float*)d_in[2],
        (const float*)d_in[3], (const float*)d_in[4], (const float*)d_in[5],
        (const float*)d_in[6], (const float*)d_in[7], (float*)d_out);
}